// round 12
// baseline (speedup 1.0000x reference)
#include <cuda_runtime.h>
#include <cuda_bf16.h>
#include <cstdint>
#include <math.h>

#define N_CLASS 50257
#define EMB 256
#define HID 512
#define BATCH 128
#define SEQ 256
#define NG 2048   // 4*HID packed gate columns (col = h*4 + g; g: 0=i,1=f,2=cand,3=o)
#define NBLK 128  // persistent grid (<=148 SMs -> co-resident; spin barrier safe)

// -------- device scratch (static globals; no cudaMalloc allowed) --------
__device__ float g_Wx[EMB * NG];                       // packed x-weights [k][h*4+g]
__device__ float g_Wh[HID * NG];                       // packed h-weights [k][h*4+g]
__device__ float g_bias[NG];                           // packed biases
__device__ float g_Gx[(size_t)SEQ * BATCH * NG];       // precomputed x-gates+bias
__device__ float g_HT[2][HID * BATCH];                 // TRANSPOSED hidden state [h][b], double-buffered

// -------- grid barrier state (flat; measured best) --------
__device__ volatile unsigned g_bar_gen;
__device__ unsigned g_bar_cnt;

// -------- f32x2 helpers (exact fp32, 2 FMA/instr) --------
typedef unsigned long long u64;
__device__ __forceinline__ void fma2(u64 &d, u64 a, u64 b) {
    asm("fma.rn.f32x2 %0,%1,%2,%0;" : "+l"(d) : "l"(a), "l"(b));
}
__device__ __forceinline__ float2 unpack2(u64 v) {
    float2 r; asm("mov.b64 {%0,%1},%2;" : "=f"(r.x), "=f"(r.y) : "l"(v)); return r;
}
__device__ __forceinline__ u64 pack2(float lo, float hi) {
    u64 r; asm("mov.b64 %0,{%1,%2};" : "=l"(r) : "f"(lo), "f"(hi)); return r;
}
// fast activations: MUFU EX2/RCP based, rel err ~2e-7 (harmless vs 1e-3 threshold)
__device__ __forceinline__ float fsig(float x)  { return __fdividef(1.f, 1.f + __expf(-x)); }
__device__ __forceinline__ float ftanh(float x) { return 1.f - __fdividef(2.f, __expf(2.f * x) + 1.f); }

__device__ __forceinline__ void grid_bar() {
    __syncthreads();
    if (threadIdx.x == 0) {
        __threadfence();
        unsigned gen = g_bar_gen;
        if (atomicAdd(&g_bar_cnt, 1u) == NBLK - 1u) {
            g_bar_cnt = 0;
            __threadfence();
            g_bar_gen = gen + 1u;
        } else {
            while (g_bar_gen == gen) { __nanosleep(32); }
            __threadfence();
        }
    }
    __syncthreads();
}

// -------- weight packing: col = h*4 + {i,f,c,o} --------
__global__ __launch_bounds__(256) void pack_kernel(
    const float* __restrict__ Wxi, const float* __restrict__ Wxf,
    const float* __restrict__ Wxo, const float* __restrict__ Wxc,
    const float* __restrict__ Whi, const float* __restrict__ Whf,
    const float* __restrict__ Who, const float* __restrict__ Whc,
    const float* __restrict__ bi,  const float* __restrict__ bf,
    const float* __restrict__ bo,  const float* __restrict__ bc)
{
    int tid = blockIdx.x * 256 + threadIdx.x;   // 0 .. 512*512-1
    int k = tid >> 9, h = tid & 511;
    int n = h * 4;
    g_Wh[k * NG + n + 0] = Whi[k * HID + h];
    g_Wh[k * NG + n + 1] = Whf[k * HID + h];
    g_Wh[k * NG + n + 2] = Whc[k * HID + h];
    g_Wh[k * NG + n + 3] = Who[k * HID + h];
    if (k < EMB) {
        g_Wx[k * NG + n + 0] = Wxi[k * HID + h];
        g_Wx[k * NG + n + 1] = Wxf[k * HID + h];
        g_Wx[k * NG + n + 2] = Wxc[k * HID + h];
        g_Wx[k * NG + n + 3] = Wxo[k * HID + h];
    }
    if (tid < HID) {
        g_bias[tid * 4 + 0] = bi[tid];
        g_bias[tid * 4 + 1] = bf[tid];
        g_bias[tid * 4 + 2] = bc[tid];
        g_bias[tid * 4 + 3] = bo[tid];
    }
}

// -------- GEMM 1: embedding gather + X@Wx + bias -> g_Gx (R5 form) --------
__global__ __launch_bounds__(256) void xgemm_kernel(
    const int* __restrict__ X, const float* __restrict__ C_emb)
{
    __shared__ float As[8][132];
    __shared__ float Bs[8][128];
    __shared__ int sIdx[BATCH];
    const int t = threadIdx.x;
    const int s = blockIdx.y;
    const int n0 = blockIdx.x * 128;
    if (t < BATCH) sIdx[t] = X[t * SEQ + s];
    __syncthreads();

    const int ar = t >> 1, ak = (t & 1) * 4;
    const int bk = t >> 5, bn = (t & 31) * 4;
    const int rowB = (t >> 4) * 8, c4 = (t & 15) * 4;
    const float* Arow = C_emb + (size_t)sIdx[ar] * EMB + ak;
    const float* Bp = g_Wx + bk * NG + n0 + bn;

    u64 acc[8][4] = {};
    for (int k0 = 0; k0 < EMB; k0 += 8) {
        float4 av = *(const float4*)(Arow + k0);
        float4 bv = *(const float4*)(Bp + (size_t)k0 * NG);
        __syncthreads();
        As[ak + 0][ar] = av.x; As[ak + 1][ar] = av.y;
        As[ak + 2][ar] = av.z; As[ak + 3][ar] = av.w;
        *(float4*)&Bs[bk][bn] = bv;
        __syncthreads();
#pragma unroll
        for (int kk = 0; kk < 8; kk++) {
            float4 a0 = *(const float4*)&As[kk][rowB];
            float4 a1 = *(const float4*)&As[kk][rowB + 4];
            ulonglong2 b0 = *(const ulonglong2*)&Bs[kk][c4];
            ulonglong2 b1 = *(const ulonglong2*)&Bs[kk][c4 + 64];
            u64 ap[8];
            ap[0] = pack2(a0.x, a0.x); ap[1] = pack2(a0.y, a0.y);
            ap[2] = pack2(a0.z, a0.z); ap[3] = pack2(a0.w, a0.w);
            ap[4] = pack2(a1.x, a1.x); ap[5] = pack2(a1.y, a1.y);
            ap[6] = pack2(a1.z, a1.z); ap[7] = pack2(a1.w, a1.w);
#pragma unroll
            for (int i = 0; i < 8; i++) {
                fma2(acc[i][0], ap[i], b0.x);
                fma2(acc[i][1], ap[i], b0.y);
                fma2(acc[i][2], ap[i], b1.x);
                fma2(acc[i][3], ap[i], b1.y);
            }
        }
    }
#pragma unroll
    for (int i = 0; i < 8; i++) {
        float* orow = g_Gx + ((size_t)(s * BATCH + rowB + i)) * NG + n0;
        float2 v0 = unpack2(acc[i][0]), v1 = unpack2(acc[i][1]);
        float2 v2 = unpack2(acc[i][2]), v3 = unpack2(acc[i][3]);
        float4 bA = *(const float4*)&g_bias[n0 + c4];
        float4 bB = *(const float4*)&g_bias[n0 + c4 + 64];
        *(float4*)(orow + c4)      = make_float4(v0.x + bA.x, v0.y + bA.y, v1.x + bA.z, v1.y + bA.w);
        *(float4*)(orow + c4 + 64) = make_float4(v2.x + bB.x, v2.y + bB.y, v3.x + bB.z, v3.y + bB.w);
    }
}

// -------- persistent recurrent kernel: NO split-K, ONE barrier per step --------
// CTA bid owns gate-cols [bid*16, bid*16+16) (= h-units bid*4..+4) over FULL K=512.
// B tile 512x16 resident. A = all of H streamed in 8 double-buffered 64-k chunks,
// duplicated in smem for direct u64 broadcast operands. Gates finish in registers;
// shfl_xor(1) exchanges (i,f)<->(cand,o) between paired threads; C in registers.
__global__ __launch_bounds__(256, 1) void rnn_persistent()
{
    extern __shared__ float sdyn[];
    float* Bs = sdyn;                    // [512][16]  32KB, persistent
    float* A0 = sdyn + 512 * 16;         // [64][256]  64KB dup chunk, ping
    float* A1 = A0 + 64 * 256;           //            64KB dup chunk, pong

    const int t = threadIdx.x;
    const int bid = blockIdx.x;
    const int bg = t >> 3;               // 0..31 -> batches [4bg, 4bg+4)
    const int cg = t & 7;                // 0..7  -> cols [2cg, 2cg+2) of my 16
    const int odd = cg & 1;
    const int ncol = bid * 16 + 2 * cg;  // global gate-col pair
    const int hg = bid * 4 + (cg >> 1);  // global h row this thread-pair fuses

    // ---- load B tile once: Bs[k][j] = Wh[k][bid*16+j] ----
#pragma unroll
    for (int j = 0; j < 8; j++) {
        int f = t + j * 256;             // float4 index 0..2047
        int k = f >> 2;
        int j4 = (f & 3) * 4;
        *(float4*)&Bs[k * 16 + j4] = *(const float4*)&g_Wh[(size_t)k * NG + bid * 16 + j4];
    }

    // ---- init H[0] slots this thread owns, C regs ----
    float cst0 = 0.f, cst1 = 0.f;
    {
        int i0 = odd ? 2 : 0;
        g_HT[0][(size_t)hg * BATCH + 4 * bg + i0]     = 0.f;
        g_HT[0][(size_t)hg * BATCH + 4 * bg + i0 + 1] = 0.f;
    }
    grid_bar();

    for (int step = 0; step < SEQ; step++) {
        const float* HT = g_HT[step & 1];

        // prefetch this step's Gx col-pair for my 4 batches (consumed in fuse)
        const float* gxb = g_Gx + ((size_t)step * BATCH + 4 * bg) * NG + ncol;
        float2 gx0 = __ldcg((const float2*)(gxb));
        float2 gx1 = __ldcg((const float2*)(gxb + NG));
        float2 gx2 = __ldcg((const float2*)(gxb + 2 * NG));
        float2 gx3 = __ldcg((const float2*)(gxb + 3 * NG));

        // ---- stage chunk 0 (dup): A[k][2b]=A[k][2b+1]=H[k][b] ----
#pragma unroll
        for (int j = 0; j < 16; j++) {
            int idx = t + j * 256;               // 0..4095
            int k = idx >> 6, b2 = (idx & 63) * 2;
            float2 v = __ldcg((const float2*)&HT[(size_t)k * BATCH + b2]);
            *(float4*)&A0[k * 256 + 2 * b2] = make_float4(v.x, v.x, v.y, v.y);
        }
        __syncthreads();

        u64 acc0 = 0, acc1 = 0, acc2 = 0, acc3 = 0;
#pragma unroll 1
        for (int kc = 0; kc < 8; kc++) {
            const float* cur = (kc & 1) ? A1 : A0;
            float* nxt = (kc & 1) ? A0 : A1;

            // issue next chunk's loads first (latency hidden under compute)
            float2 r[16];
            if (kc < 7) {
                const float* src = HT + (size_t)(kc + 1) * 64 * BATCH;
#pragma unroll
                for (int j = 0; j < 16; j++) {
                    int idx = t + j * 256;
                    int k = idx >> 6, b2 = (idx & 63) * 2;
                    r[j] = __ldcg((const float2*)&src[(size_t)k * BATCH + b2]);
                }
            }

            const float* bsrow = Bs + (kc * 64) * 16 + 2 * cg;
#pragma unroll 8
            for (int kk = 0; kk < 64; kk++) {
                const float* ar = &cur[kk * 256 + 8 * bg];
                ulonglong2 aA = *(const ulonglong2*)(ar);        // (b0,b0),(b1,b1)
                ulonglong2 aB = *(const ulonglong2*)(ar + 4);    // (b2,b2),(b3,b3)
                u64 bb = *(const u64*)(bsrow + (size_t)kk * 16); // (col, col+1)
                fma2(acc0, aA.x, bb);
                fma2(acc1, aA.y, bb);
                fma2(acc2, aB.x, bb);
                fma2(acc3, aB.y, bb);
            }

            if (kc < 7) {
#pragma unroll
                for (int j = 0; j < 16; j++) {
                    int idx = t + j * 256;
                    int k = idx >> 6, b2 = (idx & 63) * 2;
                    *(float4*)&nxt[k * 256 + 2 * b2] = make_float4(r[j].x, r[j].x, r[j].y, r[j].y);
                }
            }
            __syncthreads();
        }

        // ---- add Gx, pairwise shfl exchange, fuse; C in regs ----
        u64 tot0, tot1, tot2, tot3;
        {
            float2 a;
            a = unpack2(acc0); a.x += gx0.x; a.y += gx0.y; tot0 = pack2(a.x, a.y);
            a = unpack2(acc1); a.x += gx1.x; a.y += gx1.y; tot1 = pack2(a.x, a.y);
            a = unpack2(acc2); a.x += gx2.x; a.y += gx2.y; tot2 = pack2(a.x, a.y);
            a = unpack2(acc3); a.x += gx3.x; a.y += gx3.y; tot3 = pack2(a.x, a.y);
        }
        u64 oth0 = __shfl_xor_sync(0xffffffffu, tot0, 1);
        u64 oth1 = __shfl_xor_sync(0xffffffffu, tot1, 1);
        u64 oth2 = __shfl_xor_sync(0xffffffffu, tot2, 1);
        u64 oth3 = __shfl_xor_sync(0xffffffffu, tot3, 1);

        float* HTn = g_HT[(step + 1) & 1] + (size_t)hg * BATCH + 4 * bg;
        {
            // even thread (cols i,f) keeps batches {0,1}; odd (cols c,o) keeps {2,3}
            float2 if0 = unpack2(odd ? oth2 : tot0);   // (i,f) gate pair, pair d=0
            float2 co0 = unpack2(odd ? tot2 : oth0);   // (c,o) gate pair
            float2 if1 = unpack2(odd ? oth3 : tot1);
            float2 co1 = unpack2(odd ? tot3 : oth1);
            int i0 = odd ? 2 : 0;
            float I0 = fsig(if0.x), F0 = fsig(if0.y), T0 = ftanh(co0.x), O0 = fsig(co0.y);
            float I1 = fsig(if1.x), F1 = fsig(if1.y), T1 = ftanh(co1.x), O1 = fsig(co1.y);
            cst0 = F0 * cst0 + I0 * T0;
            cst1 = F1 * cst1 + I1 * T1;
            HTn[i0]     = O0 * ftanh(cst0);
            HTn[i0 + 1] = O1 * ftanh(cst1);
        }
        grid_bar();   // H (2KB/CTA) visible before next step
    }
}

// -------- GEMM 3: final projection H @ Whq + b_q -> out (R5 form) --------
__global__ __launch_bounds__(256) void out_gemm(
    const float* __restrict__ Whq, const float* __restrict__ bq, float* __restrict__ out)
{
    __shared__ float As[8][128];
    __shared__ float Bs[8][128];
    const int t = threadIdx.x;
    const int n0 = blockIdx.x * 128;
    const float* HT = g_HT[0];      // final H after 256 steps

    const int sk = t >> 5, sr4 = (t & 31) * 4;
    const int bk = t >> 5, bn = (t & 31) * 4;
    const int rowB = (t >> 4) * 8, c4 = (t & 15) * 4;

    u64 acc[8][4] = {};
    for (int k0 = 0; k0 < HID; k0 += 8) {
        float4 av = *(const float4*)&HT[(size_t)(k0 + sk) * BATCH + sr4];
        float bv[4];
#pragma unroll
        for (int j = 0; j < 4; j++) {
            int c = n0 + bn + j;
            bv[j] = (c < N_CLASS) ? Whq[(size_t)(k0 + bk) * N_CLASS + c] : 0.f;
        }
        __syncthreads();
        *(float4*)&As[sk][sr4] = av;
        Bs[bk][bn + 0] = bv[0]; Bs[bk][bn + 1] = bv[1];
        Bs[bk][bn + 2] = bv[2]; Bs[bk][bn + 3] = bv[3];
        __syncthreads();
#pragma unroll
        for (int kk = 0; kk < 8; kk++) {
            float4 a0 = *(const float4*)&As[kk][rowB];
            float4 a1 = *(const float4*)&As[kk][rowB + 4];
            ulonglong2 b0 = *(const ulonglong2*)&Bs[kk][c4];
            ulonglong2 b1 = *(const ulonglong2*)&Bs[kk][c4 + 64];
            u64 ap[8];
            ap[0] = pack2(a0.x, a0.x); ap[1] = pack2(a0.y, a0.y);
            ap[2] = pack2(a0.z, a0.z); ap[3] = pack2(a0.w, a0.w);
            ap[4] = pack2(a1.x, a1.x); ap[5] = pack2(a1.y, a1.y);
            ap[6] = pack2(a1.z, a1.z); ap[7] = pack2(a1.w, a1.w);
#pragma unroll
            for (int i = 0; i < 8; i++) {
                fma2(acc[i][0], ap[i], b0.x);
                fma2(acc[i][1], ap[i], b0.y);
                fma2(acc[i][2], ap[i], b1.x);
                fma2(acc[i][3], ap[i], b1.y);
            }
        }
    }
#pragma unroll
    for (int i = 0; i < 8; i++) {
        float* orow = out + (size_t)(rowB + i) * N_CLASS;
        float2 v[4] = { unpack2(acc[i][0]), unpack2(acc[i][1]),
                        unpack2(acc[i][2]), unpack2(acc[i][3]) };
        float res[8] = { v[0].x, v[0].y, v[1].x, v[1].y, v[2].x, v[2].y, v[3].x, v[3].y };
#pragma unroll
        for (int j = 0; j < 8; j++) {
            int c = n0 + ((j < 4) ? (c4 + j) : (c4 + 60 + j));
            if (c < N_CLASS) orow[c] = res[j] + bq[c];
        }
    }
}

extern "C" void kernel_launch(void* const* d_in, const int* in_sizes, int n_in,
                              void* d_out, int out_size)
{
    const int*   X     = (const int*)d_in[0];
    const float* C_emb = (const float*)d_in[1];
    const float* W_xi  = (const float*)d_in[2];
    const float* W_xf  = (const float*)d_in[3];
    const float* W_xo  = (const float*)d_in[4];
    const float* W_xc  = (const float*)d_in[5];
    const float* W_hi  = (const float*)d_in[6];
    const float* W_hf  = (const float*)d_in[7];
    const float* W_ho  = (const float*)d_in[8];
    const float* W_hc  = (const float*)d_in[9];
    const float* b_i   = (const float*)d_in[10];
    const float* b_f   = (const float*)d_in[11];
    const float* b_o   = (const float*)d_in[12];
    const float* b_c   = (const float*)d_in[13];
    const float* W_hq  = (const float*)d_in[14];
    const float* b_q   = (const float*)d_in[15];
    float* out = (float*)d_out;

    cudaFuncSetAttribute(rnn_persistent,
                         cudaFuncAttributeMaxDynamicSharedMemorySize, 160 * 1024);

    pack_kernel<<<(HID * HID) / 256, 256>>>(W_xi, W_xf, W_xo, W_xc,
                                            W_hi, W_hf, W_ho, W_hc,
                                            b_i, b_f, b_o, b_c);
    xgemm_kernel<<<dim3(NG / 128, SEQ), 256>>>(X, C_emb);
    rnn_persistent<<<NBLK, 256, 160 * 1024>>>();
    out_gemm<<<(N_CLASS + 127) / 128, 256>>>(W_hq, b_q, out);
}